// round 1
// baseline (speedup 1.0000x reference)
#include <cuda_runtime.h>

#define NKEYS 11

struct KeysArg { unsigned int a[NKEYS]; unsigned int b[NKEYS]; };

__host__ __device__ __forceinline__ unsigned int rotl32(unsigned int v, int r) {
#if defined(__CUDA_ARCH__)
  return __funnelshift_l(v, v, r);
#else
  return (v << r) | (v >> (32 - r));
#endif
}

// JAX / XLA threefry2x32 (20 rounds), exact.
__host__ __device__ __forceinline__ void threefry2x32(
    unsigned int k0, unsigned int k1, unsigned int c0, unsigned int c1,
    unsigned int& o0, unsigned int& o1) {
  unsigned int k2 = k0 ^ k1 ^ 0x1BD11BDAu;
  unsigned int x0 = c0 + k0;
  unsigned int x1 = c1 + k1;
#define TF_ROUND(r) { x0 += x1; x1 = rotl32(x1, (r)); x1 ^= x0; }
  TF_ROUND(13) TF_ROUND(15) TF_ROUND(26) TF_ROUND(6)
  x0 += k1; x1 += k2 + 1u;
  TF_ROUND(17) TF_ROUND(29) TF_ROUND(16) TF_ROUND(24)
  x0 += k2; x1 += k0 + 2u;
  TF_ROUND(13) TF_ROUND(15) TF_ROUND(26) TF_ROUND(6)
  x0 += k0; x1 += k1 + 3u;
  TF_ROUND(17) TF_ROUND(29) TF_ROUND(16) TF_ROUND(24)
  x0 += k1; x1 += k2 + 4u;
  TF_ROUND(13) TF_ROUND(15) TF_ROUND(26) TF_ROUND(6)
  x0 += k2; x1 += k0 + 5u;
#undef TF_ROUND
  o0 = x0; o1 = x1;
}

// JAX normal(): uniform in [-1,1) from top 23 bits, then XLA ErfInv32 * sqrt(2)
__device__ __forceinline__ float normal_from_u32(unsigned int bits) {
  float f = __uint_as_float((bits >> 9) | 0x3f800000u) - 1.0f;  // [0,1)
  const float lo = -0.99999994f;                                // nextafterf(-1,0)
  float u = fmaf(f, 2.0f, lo);                                  // [-1,1)
  float w = -log1pf(-u * u);
  float p;
  if (w < 5.0f) {
    w -= 2.5f;
    p =             2.81022636e-08f;
    p = fmaf(p, w,  3.43273939e-07f);
    p = fmaf(p, w, -3.5233877e-06f);
    p = fmaf(p, w, -4.39150654e-06f);
    p = fmaf(p, w,  0.00021858087f);
    p = fmaf(p, w, -0.00125372503f);
    p = fmaf(p, w, -0.00417768164f);
    p = fmaf(p, w,  0.246640727f);
    p = fmaf(p, w,  1.50140941f);
  } else {
    w = sqrtf(w) - 3.0f;
    p =            -0.000200214257f;
    p = fmaf(p, w,  0.000100950558f);
    p = fmaf(p, w,  0.00134934322f);
    p = fmaf(p, w, -0.00367342844f);
    p = fmaf(p, w,  0.00573950773f);
    p = fmaf(p, w, -0.0076224613f);
    p = fmaf(p, w,  0.00943887047f);
    p = fmaf(p, w,  1.00167406f);
    p = fmaf(p, w,  2.83297682f);
  }
  return 1.41421356f * (p * u);
}

// One warp per batch row. Lane l owns leaves [32l, 32l+32) via a stride-33
// shared-memory transpose (conflict-free both directions). Levels 0-4 are
// lane-local; levels 5-9 use warp shuffles. The 31 upper-level normals plus
// the const normal are precomputed one-per-lane (perfect threefry balance:
// exactly 32 blocks per lane).
__global__ void __launch_bounds__(256) switchbox_kernel(
    const float* __restrict__ x,
    const float* __restrict__ wsel,
    const float* __restrict__ wconst,
    float* __restrict__ out,
    KeysArg ka, int rows)
{
  __shared__ float st[8][1056];  // 32*33 per warp
  const int warp = threadIdx.x >> 5;
  const int lane = threadIdx.x & 31;
  const int row = blockIdx.x * 8 + warp;
  if (row >= rows) return;
  const unsigned int row_u = (unsigned int)row;

  const float* xr = x + (size_t)row * 1023u;
  float* stw = &st[warp][0];
#pragma unroll
  for (int k = 0; k < 32; k++) {
    int e = k * 32 + lane;
    float v = (e < 1023) ? __ldg(xr + e) : 0.0f;
    stw[k * 33 + lane] = v;  // element e stored at (e/32)*33 + (e%32)
  }
  __syncwarp();

  float v[32];
#pragma unroll
  for (int j = 0; j < 32; j++) v[j] = stw[lane * 33 + j];

  // Per-lane designated "extra" normal:
  //  lanes 0-15: level-5 m=lane | 16-23: level-6 | 24-27: level-7
  //  28-29: level-8 | 30: level-9 | 31: trained-const noise (leaf 1023)
  unsigned int ki, ctr;
  if (lane < 16)       { ki = 5;  ctr = row_u * 16u + (unsigned)lane; }
  else if (lane < 24)  { ki = 6;  ctr = row_u * 8u  + (unsigned)(lane - 16); }
  else if (lane < 28)  { ki = 7;  ctr = row_u * 4u  + (unsigned)(lane - 24); }
  else if (lane < 30)  { ki = 8;  ctr = row_u * 2u  + (unsigned)(lane - 28); }
  else if (lane == 30) { ki = 9;  ctr = row_u; }
  else                 { ki = 10; ctr = row_u; }
  unsigned int e0, e1;
  threefry2x32(ka.a[ki], ka.b[ki], 0u, ctr, e0, e1);
  float extraN = normal_from_u32(e0 ^ e1);

  if (lane == 31) {
    float pc = __ldg(wconst);
    float t = 1.0f - fabsf(pc);
    v[31] = pc + (t * t) * extraN * 0.125f;  // leaf 1023 = noisy const
  }

  // Levels 0-4: lane-local binary mux reduction
#pragma unroll
  for (int lvl = 0; lvl < 5; lvl++) {
    const int cnt = 16 >> lvl;             // outputs per lane this level
    const unsigned int nm = 512u >> lvl;   // muxes per row this level
    float p = __ldg(wsel + lvl);
    float t = 1.0f - fabsf(p);
    float sc = t * t * 0.125f;
    unsigned int base = row_u * nm + (unsigned)(lane * cnt);
#pragma unroll
    for (int j = 0; j < cnt; j++) {
      unsigned int b0, b1;
      threefry2x32(ka.a[lvl], ka.b[lvl], 0u, base + (unsigned)j, b0, b1);
      float n = normal_from_u32(b0 ^ b1);
      float s = fmaf(sc, n, p);
      float av = v[2 * j], bv = v[2 * j + 1];
      v[j] = 0.5f * ((av + bv) + s * (av - bv));
    }
  }

  // Levels 5-9: cross-lane via shuffles; normals delivered from their owner lanes
  float val = v[0];
#pragma unroll
  for (int lvl = 5; lvl <= 9; lvl++) {
    float av = __shfl_sync(0xffffffffu, val, 2 * lane);
    float bv = __shfl_sync(0xffffffffu, val, 2 * lane + 1);
    int src = (lvl == 5) ? lane
            : (lvl == 6) ? (16 + lane)
            : (lvl == 7) ? (24 + lane)
            : (lvl == 8) ? (28 + lane)
            : 30;
    float n = __shfl_sync(0xffffffffu, extraN, src);
    float p = __ldg(wsel + lvl);
    float t = 1.0f - fabsf(p);
    float sc = t * t * 0.125f;
    float s = fmaf(sc, n, p);
    val = 0.5f * ((av + bv) + s * (av - bv));
  }

  if (lane == 0) out[row] = val;
}

extern "C" void kernel_launch(void* const* d_in, const int* in_sizes, int n_in,
                              void* d_out, int out_size) {
  (void)in_sizes; (void)n_in;
  const float* x      = (const float*)d_in[0];
  const float* wsel   = (const float*)d_in[1];
  const float* wconst = (const float*)d_in[2];
  float* out = (float*)d_out;

  // keys = jax.random.split(jax.random.key(42), 11) under partitionable
  // threefry: child i = threefry((0,42), (0,i)), key = (y0, y1). Pure host math.
  KeysArg ka;
  for (unsigned int i = 0; i < NKEYS; i++) {
    threefry2x32(0u, 42u, 0u, i, ka.a[i], ka.b[i]);
  }

  int rows = out_size;                // 65536
  int blocks = (rows + 7) / 8;        // 8 warps (rows) per 256-thread block
  switchbox_kernel<<<blocks, 256>>>(x, wsel, wconst, out, ka, rows);
}

// round 3
// speedup vs baseline: 1.2420x; 1.2420x over previous
#include <cuda_runtime.h>

#define NKEYS 11

struct KeysArg { unsigned int a[NKEYS]; unsigned int b[NKEYS]; };

__host__ __device__ __forceinline__ unsigned int rotl32(unsigned int v, int r) {
#if defined(__CUDA_ARCH__)
  return __funnelshift_l(v, v, r);
#else
  return (v << r) | (v >> (32 - r));
#endif
}

// JAX / XLA threefry2x32 (20 rounds), exact.
__host__ __device__ __forceinline__ void threefry2x32(
    unsigned int k0, unsigned int k1, unsigned int c0, unsigned int c1,
    unsigned int& o0, unsigned int& o1) {
  unsigned int k2 = k0 ^ k1 ^ 0x1BD11BDAu;
  unsigned int x0 = c0 + k0;
  unsigned int x1 = c1 + k1;
#define TF_ROUND(r) { x0 += x1; x1 = rotl32(x1, (r)); x1 ^= x0; }
  TF_ROUND(13) TF_ROUND(15) TF_ROUND(26) TF_ROUND(6)
  x0 += k1; x1 += k2 + 1u;
  TF_ROUND(17) TF_ROUND(29) TF_ROUND(16) TF_ROUND(24)
  x0 += k2; x1 += k0 + 2u;
  TF_ROUND(13) TF_ROUND(15) TF_ROUND(26) TF_ROUND(6)
  x0 += k0; x1 += k1 + 3u;
  TF_ROUND(17) TF_ROUND(29) TF_ROUND(16) TF_ROUND(24)
  x0 += k1; x1 += k2 + 4u;
  TF_ROUND(13) TF_ROUND(15) TF_ROUND(26) TF_ROUND(6)
  x0 += k2; x1 += k0 + 5u;
#undef TF_ROUND
  o0 = x0; o1 = x1;
}

// JAX normal(): u in [-1,1) from top 23 bits, then sqrt(2)*ErfInv32(u).
// -log1p(-u^2) computed as -ln(fma(-u,u,1)) via MUFU.LG2, with the ln2
// scale and "-2.5" bias folded into FMAs. Polynomials pre-scaled by sqrt(2).
// NOTE: the uniform mapping MUST keep the representable bias -0.99999994f
// (= 1-2^-24). Folding it into one FMA ("-2.99999994f") rounds the constant
// to -3.0f and lets u hit exactly -1 -> log(0) -> NaN (round-2 failure).
__device__ __forceinline__ float normal_from_u32(unsigned int bits) {
  float F = __uint_as_float((bits >> 9) | 0x3f800000u);   // [1,2)
  float f = F - 1.0f;                                     // [0,1)
  float u = fmaf(f, 2.0f, -0.99999994f);                  // [-0.99999994, 1)
  float l2 = __log2f(fmaf(-u, u, 1.0f));                  // log2(1-u^2), <= 0
  const float NLN2 = -0.69314718056f;
  float w = l2 * NLN2;                                    // -ln(1-u^2) >= 0
  float p;
  if (w < 5.0f) {
    float t = fmaf(l2, NLN2, -2.5f);                      // w - 2.5
    p =             3.974270e-08f;
    p = fmaf(p, t,  4.854628e-07f);
    p = fmaf(p, t, -4.982826e-06f);
    p = fmaf(p, t, -6.210532e-06f);
    p = fmaf(p, t,  3.091220e-04f);
    p = fmaf(p, t, -1.773037e-03f);
    p = fmaf(p, t, -5.908135e-03f);
    p = fmaf(p, t,  3.488028e-01f);
    p = fmaf(p, t,  2.1233141f);
  } else {
    float t = sqrtf(w) - 3.0f;
    p =            -2.831464e-04f;
    p = fmaf(p, t,  1.427657e-04f);
    p = fmaf(p, t,  1.9082598e-03f);
    p = fmaf(p, t, -5.195011e-03f);
    p = fmaf(p, t,  8.116891e-03f);
    p = fmaf(p, t, -1.0779792e-02f);
    p = fmaf(p, t,  1.3348577e-02f);
    p = fmaf(p, t,  1.4165811f);
    p = fmaf(p, t,  4.0064335f);
  }
  return p * u;   // = sqrt(2) * erfinv(u)
}

// Mux with pre-halved, pre-biased selector constants:
//   qa = 0.5 + 0.5*s = fma(sc2, n, p2h), qb = 1 - qa, v = a*qa + b*qb
__device__ __forceinline__ float mux(float a, float b, float n,
                                     float sc2, float p2h) {
  float qa = fmaf(sc2, n, p2h);
  float qb = 1.0f - qa;
  return fmaf(a, qa, b * qb);
}

// One warp per batch row. Lane l owns leaves [32l, 32l+32) via a stride-33
// smem transpose. Level 0 is fused into the transposed read (live array is
// v[16]). Levels 1-4 lane-local, levels 5-9 via shuffles with
// pre-distributed one-normal-per-lane.
__global__ void __launch_bounds__(256, 6) switchbox_kernel(
    const float* __restrict__ x,
    const float* __restrict__ wsel,
    const float* __restrict__ wconst,
    float* __restrict__ out,
    KeysArg ka, int rows)
{
  __shared__ float st[8][1056];  // 32*33 per warp
  const int warp = threadIdx.x >> 5;
  const int lane = threadIdx.x & 31;
  const int row = blockIdx.x * 8 + warp;
  if (row >= rows) return;
  const unsigned int row_u = (unsigned int)row;

  const float* xr = x + (size_t)row * 1023u;
  float* stw = &st[warp][0];
#pragma unroll
  for (int k = 0; k < 32; k++) {
    int e = k * 32 + lane;
    float v = (e < 1023) ? __ldg(xr + e) : 0.0f;
    stw[k * 33 + lane] = v;  // element e at (e/32)*33 + (e%32)
  }
  __syncwarp();

  // Per-lane designated "extra" normal:
  //  lanes 0-15: level-5 m=lane | 16-23: level-6 | 24-27: level-7
  //  28-29: level-8 | 30: level-9 | 31: trained-const noise (leaf 1023)
  unsigned int ki, ctr;
  if (lane < 16)       { ki = 5;  ctr = row_u * 16u + (unsigned)lane; }
  else if (lane < 24)  { ki = 6;  ctr = row_u * 8u  + (unsigned)(lane - 16); }
  else if (lane < 28)  { ki = 7;  ctr = row_u * 4u  + (unsigned)(lane - 24); }
  else if (lane < 30)  { ki = 8;  ctr = row_u * 2u  + (unsigned)(lane - 28); }
  else if (lane == 30) { ki = 9;  ctr = row_u; }
  else                 { ki = 10; ctr = row_u; }
  unsigned int e0, e1;
  threefry2x32(ka.a[ki], ka.b[ki], 0u, ctr, e0, e1);
  float extraN = normal_from_u32(e0 ^ e1);

  // Lane 31's extra normal is the trained-const noise (leaf 1023)
  float pc = __ldg(wconst);
  float tc = 1.0f - fabsf(pc);
  float cval = fmaf(tc * tc * 0.125f, extraN, pc);

  // ---- Level 0 fused with transposed smem read ----
  float v[16];
  {
    float p = __ldg(wsel + 0);
    float t = 1.0f - fabsf(p);
    float sc2 = t * t * 0.0625f;        // 0.5 * t^2 * 0.125
    float p2h = fmaf(p, 0.5f, 0.5f);    // 0.5 + 0.5*p
    unsigned int base = row_u * 512u + (unsigned)(lane * 16);
    const float* src = stw + lane * 33;
#pragma unroll
    for (int j = 0; j < 16; j++) {
      unsigned int b0, b1;
      threefry2x32(ka.a[0], ka.b[0], 0u, base + (unsigned)j, b0, b1);
      float n = normal_from_u32(b0 ^ b1);
      float av = src[2 * j];
      float bv = src[2 * j + 1];
      if (j == 15 && lane == 31) bv = cval;   // leaf 1023 = noisy const
      v[j] = mux(av, bv, n, sc2, p2h);
    }
  }

  // ---- Levels 1-4: lane-local ----
#pragma unroll
  for (int lvl = 1; lvl < 5; lvl++) {
    const int cnt = 16 >> lvl;
    const unsigned int nm = 512u >> lvl;
    float p = __ldg(wsel + lvl);
    float t = 1.0f - fabsf(p);
    float sc2 = t * t * 0.0625f;
    float p2h = fmaf(p, 0.5f, 0.5f);
    unsigned int base = row_u * nm + (unsigned)(lane * cnt);
#pragma unroll
    for (int j = 0; j < cnt; j++) {
      unsigned int b0, b1;
      threefry2x32(ka.a[lvl], ka.b[lvl], 0u, base + (unsigned)j, b0, b1);
      float n = normal_from_u32(b0 ^ b1);
      v[j] = mux(v[2 * j], v[2 * j + 1], n, sc2, p2h);
    }
  }

  // ---- Levels 5-9: cross-lane via shuffles ----
  float val = v[0];
#pragma unroll
  for (int lvl = 5; lvl <= 9; lvl++) {
    float av = __shfl_sync(0xffffffffu, val, 2 * lane);
    float bv = __shfl_sync(0xffffffffu, val, 2 * lane + 1);
    int src = (lvl == 5) ? lane
            : (lvl == 6) ? (16 + lane)
            : (lvl == 7) ? (24 + lane)
            : (lvl == 8) ? (28 + lane)
            : 30;
    float n = __shfl_sync(0xffffffffu, extraN, src);
    float p = __ldg(wsel + lvl);
    float t = 1.0f - fabsf(p);
    float sc2 = t * t * 0.0625f;
    float p2h = fmaf(p, 0.5f, 0.5f);
    val = mux(av, bv, n, sc2, p2h);
  }

  if (lane == 0) out[row] = val;
}

extern "C" void kernel_launch(void* const* d_in, const int* in_sizes, int n_in,
                              void* d_out, int out_size) {
  (void)in_sizes; (void)n_in;
  const float* x      = (const float*)d_in[0];
  const float* wsel   = (const float*)d_in[1];
  const float* wconst = (const float*)d_in[2];
  float* out = (float*)d_out;

  // keys = jax.random.split(jax.random.key(42), 11) under partitionable
  // threefry: child i = threefry((0,42), (0,i)). Pure host math.
  KeysArg ka;
  for (unsigned int i = 0; i < NKEYS; i++) {
    threefry2x32(0u, 42u, 0u, i, ka.a[i], ka.b[i]);
  }

  int rows = out_size;                // 65536
  int blocks = (rows + 7) / 8;        // 8 warps (rows) per 256-thread block
  switchbox_kernel<<<blocks, 256>>>(x, wsel, wconst, out, ka, rows);
}